// round 7
// baseline (speedup 1.0000x reference)
#include <cuda_runtime.h>

// HyperComplexAdapterBlock: y = phm_up(gelu_new(phm_down(x))), rank-1 PHM.
// R7: ZERO smem staging. Lane (g=l/8, k=l%8) owns float4 indices
// {48g + k + 8m, m=0..5} of each token: all inside a-block g (so the 8-lane
// group-reduce still covers exactly one block), AND each LDG/STG instruction
// (fixed m) touches 4 aligned full 128B lines (one per group) -> sector-exact
// global traffic with NO transpose stage. Weight addresses depend only on
// k -> 8 distinct addrs/warp -> 1-wavefront broadcast LDS. This removes the
// ~96 wf/token of stage round trips that made L1 the cap (73%) in R6.

typedef unsigned long long u64;

__device__ __forceinline__ u64 fma2(u64 a, u64 b, u64 c) {
    u64 d;
    asm("fma.rn.f32x2 %0, %1, %2, %3;" : "=l"(d) : "l"(a), "l"(b), "l"(c));
    return d;
}
__device__ __forceinline__ float sum2(u64 v) {
    float a, b; asm("mov.b64 {%0, %1}, %2;" : "=f"(a), "=f"(b) : "l"(v));
    return a + b;
}
__device__ __forceinline__ u64 pk2(float lo, float hi) {
    u64 r; asm("mov.b64 %0, {%1, %2};" : "=l"(r) : "f"(lo), "f"(hi));
    return r;
}
__device__ __forceinline__ float tanh_fast(float x) {
    float y; asm("tanh.approx.f32 %0, %1;" : "=f"(y) : "f"(x));
    return y;
}

#define NW 4          // warps per CTA
#define NT 128        // threads per CTA
#define TPI 3         // tokens per warp-iteration

__global__ __launch_bounds__(NT, 5)
void phm_fused_kernel(const float* __restrict__ x,
                      const float* __restrict__ rule_d,
                      const float* __restrict__ Ld,
                      const float* __restrict__ Rd,
                      const float* __restrict__ bd,
                      const float* __restrict__ rule_u,
                      const float* __restrict__ Lu,
                      const float* __restrict__ Ru,
                      const float* __restrict__ bu,
                      float* __restrict__ out,
                      int ntok)
{
    __shared__ ulonglong2 pLd[192];   // Ld  as float4[i*48 + q4]
    __shared__ ulonglong2 pRu[192];   // Ru  as float4[i*48 + q4]
    __shared__ ulonglong2 sBu[192];   // bu  as float4[f]
    __shared__ float2     pRL[192];   // (Rd, Lu)[i*48 + q]
    __shared__ float      sRd[64], sRu[64];

    const int tid = threadIdx.x;
    const ulonglong2* Ld2 = (const ulonglong2*)Ld;
    const ulonglong2* Ru2 = (const ulonglong2*)Ru;
    const ulonglong2* bu2 = (const ulonglong2*)bu;

    for (int idx = tid; idx < 192; idx += NT) {
        pLd[idx] = Ld2[idx];
        pRu[idx] = Ru2[idx];
        sBu[idx] = bu2[idx];
        pRL[idx] = make_float2(Rd[idx], Lu[idx]);
    }
    for (int idx = tid; idx < 64; idx += NT) {
        sRd[idx] = rule_d[idx];
        sRu[idx] = rule_u[idx];
    }
    __syncthreads();

    const int l = tid & 31;
    const int w = tid >> 5;
    const int g = l >> 3;        // group: a on input side, c on z/output side
    const int k = l & 7;

    // token-invariant: bias_d at lane's z slots q = k + 8m
    float biasD[6];
#pragma unroll
    for (int m = 0; m < 6; m++)
        biasD[m] = bd[48*g + k + 8*m];

    const ulonglong2* x2 = (const ulonglong2*)x;
    ulonglong2*       o2 = (ulonglong2*)out;

    const int gwarp = blockIdx.x * NW + w;
    const int nwarp = gridDim.x * NW;
    const int fbase = 48*g + k;  // lane's f4 base within a token row

    for (int base = gwarp * TPI; base < ntok; base += nwarp * TPI) {
        size_t row[TPI];
#pragma unroll
        for (int tt = 0; tt < TPI; tt++) {
            int t = base + tt; if (t > ntok - 1) t = ntok - 1;
            row[tt] = (size_t)t * 192 + fbase;
        }

        // ---- down stage 1: direct strided-by-8 loads (full sectors) ----
        u64 si2[TPI][4];
#pragma unroll
        for (int tt = 0; tt < TPI; tt++)
#pragma unroll
            for (int i = 0; i < 4; i++) si2[tt][i] = 0ull;

#pragma unroll
        for (int m = 0; m < 6; m++) {
            ulonglong2 u[TPI];
#pragma unroll
            for (int tt = 0; tt < TPI; tt++)
                u[tt] = x2[row[tt] + 8*m];
#pragma unroll
            for (int i = 0; i < 4; i++) {
                ulonglong2 wv = pLd[i*48 + k + 8*m];   // 8 addrs, 4-way bcast
#pragma unroll
                for (int tt = 0; tt < TPI; tt++) {
                    si2[tt][i] = fma2(u[tt].x, wv.x, si2[tt][i]);
                    si2[tt][i] = fma2(u[tt].y, wv.y, si2[tt][i]);
                }
            }
        }
        float si[TPI][4];
#pragma unroll
        for (int tt = 0; tt < TPI; tt++)
#pragma unroll
            for (int i = 0; i < 4; i++) {
                float v = sum2(si2[tt][i]);
                v += __shfl_xor_sync(0xffffffffu, v, 4);
                v += __shfl_xor_sync(0xffffffffu, v, 2);
                v += __shfl_xor_sync(0xffffffffu, v, 1);
                si[tt][i] = v;
            }

        // ---- down stage 2: t[c][i] (c = g) ----
        float tD[TPI][4];
#pragma unroll
        for (int tt = 0; tt < TPI; tt++)
#pragma unroll
            for (int i = 0; i < 4; i++) tD[tt][i] = 0.f;
#pragma unroll
        for (int a = 0; a < 4; a++)
#pragma unroll
            for (int i = 0; i < 4; i++) {
                float r = sRd[i*16 + a*4 + g];
#pragma unroll
                for (int tt = 0; tt < TPI; tt++)
                    tD[tt][i] = fmaf(r, __shfl_sync(0xffffffffu, si[tt][i], a*8 + k),
                                     tD[tt][i]);
            }

        // ---- fused z -> gelu_new -> up stage 1 (s2); lane's z: q = k+8m ----
        float s2[TPI][4];
#pragma unroll
        for (int tt = 0; tt < TPI; tt++)
#pragma unroll
            for (int i = 0; i < 4; i++) s2[tt][i] = 0.f;

#pragma unroll
        for (int m = 0; m < 6; m++) {
            float2 rl[4];
#pragma unroll
            for (int i = 0; i < 4; i++) rl[i] = pRL[i*48 + k + 8*m];
            float zv[TPI];
#pragma unroll
            for (int tt = 0; tt < TPI; tt++) zv[tt] = biasD[m];
#pragma unroll
            for (int i = 0; i < 4; i++)
#pragma unroll
                for (int tt = 0; tt < TPI; tt++)
                    zv[tt] = fmaf(tD[tt][i], rl[i].x, zv[tt]);
#pragma unroll
            for (int tt = 0; tt < TPI; tt++) {
                float z   = zv[tt];
                float arg = 0.7978845608028654f * fmaf(0.044715f*z, z*z, z);
                float h   = 0.5f * z;
                zv[tt] = fmaf(h, tanh_fast(arg), h);   // 0.5z(1+tanh)
            }
#pragma unroll
            for (int i = 0; i < 4; i++)
#pragma unroll
                for (int tt = 0; tt < TPI; tt++)
                    s2[tt][i] = fmaf(zv[tt], rl[i].y, s2[tt][i]);
        }
#pragma unroll
        for (int tt = 0; tt < TPI; tt++)
#pragma unroll
            for (int i = 0; i < 4; i++) {
                float v = s2[tt][i];
                v += __shfl_xor_sync(0xffffffffu, v, 4);
                v += __shfl_xor_sync(0xffffffffu, v, 2);
                v += __shfl_xor_sync(0xffffffffu, v, 1);
                s2[tt][i] = v;
            }

        // ---- up stage 2: tU[c][i] (c = g), packed ----
        u64 tUp[TPI][4];
#pragma unroll
        for (int tt = 0; tt < TPI; tt++)
#pragma unroll
            for (int i = 0; i < 4; i++) {
                float acc = 0.f;
#pragma unroll
                for (int a = 0; a < 4; a++)
                    acc = fmaf(sRu[i*16 + a*4 + g],
                               __shfl_sync(0xffffffffu, s2[tt][i], a*8 + k), acc);
                tUp[tt][i] = pk2(acc, acc);
            }

        // ---- output: direct strided-by-8 stores (full 128B lines) ----
#pragma unroll
        for (int m = 0; m < 6; m++) {
            ulonglong2 rv[4];
#pragma unroll
            for (int i = 0; i < 4; i++) rv[i] = pRu[i*48 + k + 8*m];
            ulonglong2 bb = sBu[fbase + 8*m];
#pragma unroll
            for (int tt = 0; tt < TPI; tt++) {
                ulonglong2 o = bb;
#pragma unroll
                for (int i = 0; i < 4; i++) {
                    o.x = fma2(tUp[tt][i], rv[i].x, o.x);
                    o.y = fma2(tUp[tt][i], rv[i].y, o.y);
                }
                if (base + tt < ntok)
                    o2[row[tt] + 8*m] = o;
            }
        }
    }
}

extern "C" void kernel_launch(void* const* d_in, const int* in_sizes, int n_in,
                              void* d_out, int out_size)
{
    const float* x      = (const float*)d_in[0];
    const float* rule_d = (const float*)d_in[1];
    const float* Ld     = (const float*)d_in[2];
    const float* Rd     = (const float*)d_in[3];
    const float* bd     = (const float*)d_in[4];
    const float* rule_u = (const float*)d_in[5];
    const float* Lu     = (const float*)d_in[6];
    const float* Ru     = (const float*)d_in[7];
    const float* bu     = (const float*)d_in[8];

    const int ntok = in_sizes[0] / 768;

    // 148 SMs * 5 CTAs (128 thr, ~11KB smem) persistent grid-stride
    phm_fused_kernel<<<740, NT>>>(x, rule_d, Ld, Rd, bd,
                                  rule_u, Lu, Ru, bu,
                                  (float*)d_out, ntok);
}